// round 2
// baseline (speedup 1.0000x reference)
#include <cuda_runtime.h>
#include <cstdint>

#define Nn 50000
#define Ee 800000
#define Hh 4
#define Cc 64
#define Gg 64

// ---------------- scratch (device globals: no allocation allowed) ----------
__device__ float    g_x[(size_t)Nn * Hh * Cc];   // 51.2 MB projected features
__device__ float    g_asrc[Nn * Hh];
__device__ float    g_adst[Nn * Hh];
__device__ float    g_alpha[(size_t)Ee * Hh];    // alpha, then ex (reused)
__device__ unsigned g_amax[Nn * Hh];             // ordered-key float max
__device__ float    g_denom[Nn * Hh];
__device__ float    g_out[(size_t)Nn * Cc];      // scatter accumulator -> normalized feature
__device__ float    g_M[16 * 4];                 // edge-attr collapse matrix
__device__ float    g_gsum[Gg * Cc];
__device__ float    g_gcnt[Gg];
__device__ float    g_mean[Gg * Cc];
__device__ float    g_vsum[Gg * Cc];
__device__ float    g_rstd[Gg * Cc];

// monotone key: float -> unsigned preserving order for atomicMax
__device__ __forceinline__ unsigned fkey(float f) {
    unsigned b = __float_as_uint(f);
    return (b & 0x80000000u) ? ~b : (b | 0x80000000u);
}
__device__ __forceinline__ float fdec(unsigned u) {
    return __uint_as_float((u & 0x80000000u) ? (u ^ 0x80000000u) : ~u);
}

// ---------------- init ----------------
__global__ void k_init() {
    int stride = gridDim.x * blockDim.x;
    for (int idx = blockIdx.x * blockDim.x + threadIdx.x; idx < Nn * Cc; idx += stride) {
        g_out[idx] = 0.f;
        if (idx < Nn * Hh) { g_amax[idx] = 0u; g_denom[idx] = 0.f; }
        if (idx < Gg * Cc) { g_gsum[idx] = 0.f; g_vsum[idx] = 0.f; }
        if (idx < Gg)      { g_gcnt[idx] = 0.f; }
    }
}

// ---------------- node projection + attention dot products ----------------
// block = 256 threads; thread j owns output column j (= h*64 + c).
// W column cached in registers; node row broadcast via smem.
__global__ void k_proj(const float* __restrict__ node, const float* __restrict__ W,
                       const float* __restrict__ att_src, const float* __restrict__ att_dst) {
    const int j = threadIdx.x;
    float w[64];
#pragma unroll
    for (int k = 0; k < 64; k++) w[k] = W[k * 256 + j];
    const float asv = att_src[j];
    const float adv = att_dst[j];

    __shared__ float row[64];
    __shared__ float redS[8], redD[8];
    const int warp = j >> 5, lane = j & 31, h = j >> 6;

    for (int n = blockIdx.x; n < Nn; n += gridDim.x) {
        __syncthreads();
        if (j < 16) ((float4*)row)[j] = ((const float4*)(node + (size_t)n * 64))[j];
        __syncthreads();
        float acc = 0.f;
#pragma unroll
        for (int k = 0; k < 64; k++) acc = fmaf(w[k], row[k], acc);
        g_x[(size_t)n * 256 + j] = acc;

        float s = acc * asv, t = acc * adv;
#pragma unroll
        for (int o = 16; o; o >>= 1) {
            s += __shfl_down_sync(0xffffffffu, s, o);
            t += __shfl_down_sync(0xffffffffu, t, o);
        }
        if (lane == 0) { redS[warp] = s; redD[warp] = t; }
        __syncthreads();
        if (lane == 0 && (warp & 1) == 0) {
            g_asrc[n * 4 + h] = redS[warp] + redS[warp + 1];
            g_adst[n * 4 + h] = redD[warp] + redD[warp + 1];
        }
    }
}

// ---------------- edge-attr collapse matrix M[16,4] ----------------
// M[d,h] = sum_c W_edge[d, h*64+c] * att_edge[h,c]
__global__ void k_medge(const float* __restrict__ We, const float* __restrict__ ae) {
    int t = threadIdx.x;            // 0..63
    int d = t >> 2, h = t & 3;
    float s = 0.f;
    for (int c = 0; c < 64; c++) s += We[d * 256 + h * 64 + c] * ae[h * 64 + c];
    g_M[d * 4 + h] = s;
}

// ---------------- alpha = leaky(a_src[s] + a_dst[d] + ea@M), segment max ----
__global__ void k_alpha(const int* __restrict__ ei, const float* __restrict__ ea) {
    int stride = gridDim.x * blockDim.x;
    for (int e = blockIdx.x * blockDim.x + threadIdx.x; e < Ee; e += stride) {
        int s = ei[e], d = ei[Ee + e];
        float aeh[4] = {0.f, 0.f, 0.f, 0.f};
        const float4* ep = (const float4*)(ea + (size_t)e * 16);
#pragma unroll
        for (int q = 0; q < 4; q++) {
            float4 v = ep[q];
#pragma unroll
            for (int h = 0; h < 4; h++) {
                aeh[h] += v.x * g_M[(q * 4 + 0) * 4 + h]
                        + v.y * g_M[(q * 4 + 1) * 4 + h]
                        + v.z * g_M[(q * 4 + 2) * 4 + h]
                        + v.w * g_M[(q * 4 + 3) * 4 + h];
            }
        }
        float4 as4 = *(const float4*)(g_asrc + s * 4);
        float4 ad4 = *(const float4*)(g_adst + d * 4);
        float al[4] = { as4.x + ad4.x + aeh[0], as4.y + ad4.y + aeh[1],
                        as4.z + ad4.z + aeh[2], as4.w + ad4.w + aeh[3] };
#pragma unroll
        for (int h = 0; h < 4; h++) al[h] = (al[h] > 0.f) ? al[h] : 0.2f * al[h];
        *(float4*)(g_alpha + (size_t)e * 4) = make_float4(al[0], al[1], al[2], al[3]);
#pragma unroll
        for (int h = 0; h < 4; h++) atomicMax(&g_amax[d * 4 + h], fkey(al[h]));
    }
}

// ---------------- ex = exp(alpha - amax[dst]); denom accumulate ------------
__global__ void k_exp(const int* __restrict__ ei) {
    int stride = gridDim.x * blockDim.x;
    for (int e = blockIdx.x * blockDim.x + threadIdx.x; e < Ee; e += stride) {
        int d = ei[Ee + e];
        float4 al = *(const float4*)(g_alpha + (size_t)e * 4);
        uint4 mu = *(const uint4*)(g_amax + d * 4);
        float e0 = __expf(al.x - fdec(mu.x));
        float e1 = __expf(al.y - fdec(mu.y));
        float e2 = __expf(al.z - fdec(mu.z));
        float e3 = __expf(al.w - fdec(mu.w));
        *(float4*)(g_alpha + (size_t)e * 4) = make_float4(e0, e1, e2, e3);
        atomicAdd(&g_denom[d * 4 + 0], e0);
        atomicAdd(&g_denom[d * 4 + 1], e1);
        atomicAdd(&g_denom[d * 4 + 2], e2);
        atomicAdd(&g_denom[d * 4 + 3], e3);
    }
}

// ---------------- att = ex/denom; head-folded scatter add ------------------
// One warp per edge. m[c] = sum_h att[h] * x[src, h, c]  -> red to g_out[dst, c].
__global__ void k_scatter(const int* __restrict__ ei, float* __restrict__ att_out) {
    int lane = threadIdx.x & 31;
    int w = (blockIdx.x * blockDim.x + threadIdx.x) >> 5;
    int nw = (gridDim.x * blockDim.x) >> 5;
    for (int e = w; e < Ee; e += nw) {
        int s = ei[e], d = ei[Ee + e];
        float4 ex4 = *(const float4*)(g_alpha + (size_t)e * 4);
        float4 dn4 = *(const float4*)(g_denom + d * 4);
        float a0 = ex4.x / (dn4.x + 1e-16f);
        float a1 = ex4.y / (dn4.y + 1e-16f);
        float a2 = ex4.z / (dn4.z + 1e-16f);
        float a3 = ex4.w / (dn4.w + 1e-16f);
        if (lane == 0)
            *(float4*)(att_out + (size_t)e * 4) = make_float4(a0, a1, a2, a3);
        const float2* xp = (const float2*)(g_x + (size_t)s * 256);
        float2 v0 = xp[lane], v1 = xp[32 + lane], v2 = xp[64 + lane], v3 = xp[96 + lane];
        float m0 = a0 * v0.x + a1 * v1.x + a2 * v2.x + a3 * v3.x;
        float m1 = a0 * v0.y + a1 * v1.y + a2 * v2.y + a3 * v3.y;
        float* op = g_out + (size_t)d * 64 + 2 * lane;
        atomicAdd(op, m0);
        atomicAdd(op + 1, m1);
    }
}

// ---------------- GraphNorm stage 1: head mean + bias, group sums ----------
__global__ void k_gsum(const int* __restrict__ bptr, const float* __restrict__ bias) {
    int stride = gridDim.x * blockDim.x;
    for (int idx = blockIdx.x * blockDim.x + threadIdx.x; idx < Nn * Cc; idx += stride) {
        int n = idx >> 6, c = idx & 63;
        int g = bptr[n];
        float v = g_out[idx] * 0.25f + bias[c];
        g_out[idx] = v;
        atomicAdd(&g_gsum[g * 64 + c], v);
        if (c == 0) atomicAdd(&g_gcnt[g], 1.0f);
    }
}

__global__ void k_mean() {
    int idx = blockIdx.x * blockDim.x + threadIdx.x;
    if (idx < Gg * Cc) {
        float cnt = fmaxf(g_gcnt[idx >> 6], 1.0f);
        g_mean[idx] = g_gsum[idx] / cnt;
    }
}

__global__ void k_var(const int* __restrict__ bptr, const float* __restrict__ gns) {
    int stride = gridDim.x * blockDim.x;
    for (int idx = blockIdx.x * blockDim.x + threadIdx.x; idx < Nn * Cc; idx += stride) {
        int n = idx >> 6, c = idx & 63;
        int g = bptr[n];
        float o = g_out[idx] - g_mean[g * 64 + c] * gns[c];
        atomicAdd(&g_vsum[g * 64 + c], o * o);
    }
}

__global__ void k_rstd() {
    int idx = blockIdx.x * blockDim.x + threadIdx.x;
    if (idx < Gg * Cc) {
        float cnt = fmaxf(g_gcnt[idx >> 6], 1.0f);
        g_rstd[idx] = rsqrtf(g_vsum[idx] / cnt + 1e-5f);
    }
}

__global__ void k_final(const int* __restrict__ bptr, const float* __restrict__ gns,
                        const float* __restrict__ gnw, const float* __restrict__ gnb,
                        float* __restrict__ y) {
    int stride = gridDim.x * blockDim.x;
    for (int idx = blockIdx.x * blockDim.x + threadIdx.x; idx < Nn * Cc; idx += stride) {
        int n = idx >> 6, c = idx & 63;
        int g = bptr[n];
        float o = g_out[idx] - g_mean[g * 64 + c] * gns[c];
        float v = gnw[c] * (o * g_rstd[g * 64 + c]) + gnb[c];
        y[idx] = fmaxf(v, 0.f);
    }
}

// ---------------- launch ----------------
extern "C" void kernel_launch(void* const* d_in, const int* in_sizes, int n_in,
                              void* d_out, int out_size) {
    const float* node = (const float*)d_in[0];
    const int*   ei   = (const int*)  d_in[1];   // [2,E]: src then dst
    const float* ea   = (const float*)d_in[2];
    const int*   bptr = (const int*)  d_in[3];
    const float* W    = (const float*)d_in[4];
    const float* We   = (const float*)d_in[5];
    const float* asv  = (const float*)d_in[6];
    const float* adv  = (const float*)d_in[7];
    const float* aev  = (const float*)d_in[8];
    const float* bias = (const float*)d_in[9];
    const float* gnw  = (const float*)d_in[10];
    const float* gnb  = (const float*)d_in[11];
    const float* gns  = (const float*)d_in[12];

    float* y       = (float*)d_out;           // [N, C] first
    float* att_out = y + (size_t)Nn * Cc;     // [E, H] second

    k_init   <<<1024, 256>>>();
    k_proj   <<<2048, 256>>>(node, W, asv, adv);
    k_medge  <<<1, 64>>>(We, aev);
    k_alpha  <<<2048, 256>>>(ei, ea);
    k_exp    <<<2048, 256>>>(ei);
    k_scatter<<<4096, 256>>>(ei, att_out);
    k_gsum   <<<2048, 256>>>(bptr, bias);
    k_mean   <<<16, 256>>>();
    k_var    <<<2048, 256>>>(bptr, gns);
    k_rstd   <<<16, 256>>>();
    k_final  <<<2048, 256>>>(bptr, gns, gnw, gnb, y);
}

// round 3
// speedup vs baseline: 1.0541x; 1.0541x over previous
#include <cuda_runtime.h>
#include <cstdint>

#define Nn 50000
#define Ee 800000
#define Hh 4
#define Cc 64
#define Gg 64

// ---------------- scratch (device globals: no allocation allowed) ----------
__device__ float g_x[(size_t)Nn * Hh * Cc];   // 51.2 MB projected features
__device__ float g_asrc[Nn * Hh];
__device__ float g_adst[Nn * Hh];
__device__ float g_ex[(size_t)Ee * Hh];       // exp(alpha)
__device__ float g_denom[Nn * Hh];
__device__ float g_out[(size_t)Nn * Cc];      // scatter accumulator (raw, pre bias/mean)
__device__ float g_M[16 * 4];                 // edge-attr collapse matrix
__device__ float g_gsum[Gg * Cc];             // sum of raw out per (group, channel)
__device__ float g_vsum[Gg * Cc];             // sum of raw out^2
__device__ float g_gcnt[Gg];
__device__ float g_mean[Gg * Cc];             // E[out]*gn_scale (pre-multiplied)
__device__ float g_rstd[Gg * Cc];

__device__ __forceinline__ void red4(float* p, float4 v) {
    asm volatile("red.global.add.v4.f32 [%0], {%1,%2,%3,%4};"
                 :: "l"(p), "f"(v.x), "f"(v.y), "f"(v.z), "f"(v.w) : "memory");
}

// ---------------- init ----------------
__global__ void k_init() {
    int stride = gridDim.x * blockDim.x;
    float4 z = make_float4(0.f, 0.f, 0.f, 0.f);
    for (int i = blockIdx.x * blockDim.x + threadIdx.x; i < Nn * Cc / 4; i += stride) {
        ((float4*)g_out)[i] = z;
        if (i < Nn * Hh / 4) ((float4*)g_denom)[i] = z;
        if (i < Gg * Cc / 4) { ((float4*)g_gsum)[i] = z; ((float4*)g_vsum)[i] = z; }
        if (i < Gg / 4)      ((float4*)g_gcnt)[i] = z;
    }
}

// ---------------- node projection + attention dot products ----------------
// 256 threads; thread j owns output column j. W column in registers,
// node row broadcast via smem with register double-buffered prefetch.
__global__ void k_proj(const float* __restrict__ node, const float* __restrict__ W,
                       const float* __restrict__ att_src, const float* __restrict__ att_dst) {
    const int j = threadIdx.x;
    float w[64];
#pragma unroll
    for (int k = 0; k < 64; k++) w[k] = W[k * 256 + j];
    const float asv = att_src[j];
    const float adv = att_dst[j];

    __shared__ float row[64];
    __shared__ float redS[8], redD[8];
    const int warp = j >> 5, lane = j & 31, h = j >> 6;

    int n = blockIdx.x;
    float4 pre = make_float4(0.f, 0.f, 0.f, 0.f);
    if (n < Nn && j < 16) pre = ((const float4*)(node + (size_t)n * 64))[j];

    while (n < Nn) {
        if (j < 16) ((float4*)row)[j] = pre;
        __syncthreads();
        int nn = n + gridDim.x;
        if (nn < Nn && j < 16) pre = ((const float4*)(node + (size_t)nn * 64))[j];

        float acc = 0.f;
#pragma unroll
        for (int k = 0; k < 64; k++) acc = fmaf(w[k], row[k], acc);
        g_x[(size_t)n * 256 + j] = acc;

        float s = acc * asv, t = acc * adv;
#pragma unroll
        for (int o = 16; o; o >>= 1) {
            s += __shfl_down_sync(0xffffffffu, s, o);
            t += __shfl_down_sync(0xffffffffu, t, o);
        }
        if (lane == 0) { redS[warp] = s; redD[warp] = t; }
        __syncthreads();
        if (lane == 0 && (warp & 1) == 0) {
            g_asrc[n * 4 + h] = redS[warp] + redS[warp + 1];
            g_adst[n * 4 + h] = redD[warp] + redD[warp + 1];
        }
        n = nn;
    }
}

// ---------------- edge-attr collapse matrix M[16,4] ----------------
__global__ void k_medge(const float* __restrict__ We, const float* __restrict__ ae) {
    int t = threadIdx.x;            // 0..63
    int d = t >> 2, h = t & 3;
    float s = 0.f;
    for (int c = 0; c < 64; c++) s += We[d * 256 + h * 64 + c] * ae[h * 64 + c];
    g_M[d * 4 + h] = s;
}

// ---- alpha = leaky(a_src[s]+a_dst[d]+ea@M); ex=exp(alpha); denom RED -----
// No max subtraction: exp(a-m)/sum == exp(a)/sum exactly; |alpha| <~ 16 here
// so fp32 exp is safe.  M lives in smem -> low regs, high occupancy.
__global__ void k_alpha(const int* __restrict__ ei, const float* __restrict__ ea) {
    __shared__ float Ms[64];
    if (threadIdx.x < 64) Ms[threadIdx.x] = g_M[threadIdx.x];
    __syncthreads();
    int stride = gridDim.x * blockDim.x;
    for (int e = blockIdx.x * blockDim.x + threadIdx.x; e < Ee; e += stride) {
        int s = ei[e], d = ei[Ee + e];
        float aeh[4] = {0.f, 0.f, 0.f, 0.f};
        const float4* ep = (const float4*)(ea + (size_t)e * 16);
#pragma unroll
        for (int q = 0; q < 4; q++) {
            float4 v = ep[q];
#pragma unroll
            for (int h = 0; h < 4; h++) {
                aeh[h] += v.x * Ms[(q * 4 + 0) * 4 + h]
                        + v.y * Ms[(q * 4 + 1) * 4 + h]
                        + v.z * Ms[(q * 4 + 2) * 4 + h]
                        + v.w * Ms[(q * 4 + 3) * 4 + h];
            }
        }
        float4 as4 = *(const float4*)(g_asrc + s * 4);
        float4 ad4 = *(const float4*)(g_adst + d * 4);
        float al0 = as4.x + ad4.x + aeh[0];
        float al1 = as4.y + ad4.y + aeh[1];
        float al2 = as4.z + ad4.z + aeh[2];
        float al3 = as4.w + ad4.w + aeh[3];
        al0 = (al0 > 0.f) ? al0 : 0.2f * al0;
        al1 = (al1 > 0.f) ? al1 : 0.2f * al1;
        al2 = (al2 > 0.f) ? al2 : 0.2f * al2;
        al3 = (al3 > 0.f) ? al3 : 0.2f * al3;
        float4 ex = make_float4(__expf(al0), __expf(al1), __expf(al2), __expf(al3));
        *(float4*)(g_ex + (size_t)e * 4) = ex;
        red4(&g_denom[d * 4], ex);
    }
}

// ---------------- att = ex/denom; head-folded scatter (v4 RED) -------------
// Half-warp per edge: lane handles 4 channels; 16 x 128-bit REDs per edge.
__global__ void k_scatter(const int* __restrict__ ei, float* __restrict__ att_out) {
    int tid = blockIdx.x * blockDim.x + threadIdx.x;
    int lane = threadIdx.x & 31;
    int half = lane >> 4;       // which edge of the pair
    int sub = lane & 15;        // channel quad index
    int w = tid >> 5;
    int nw = (gridDim.x * blockDim.x) >> 5;
    for (int e = w * 2 + half; e < Ee; e += nw * 2) {
        int s = ei[e], d = ei[Ee + e];
        float4 ex4 = *(const float4*)(g_ex + (size_t)e * 4);
        float4 dn4 = *(const float4*)(g_denom + (size_t)d * 4);
        float a0 = ex4.x / (dn4.x + 1e-16f);
        float a1 = ex4.y / (dn4.y + 1e-16f);
        float a2 = ex4.z / (dn4.z + 1e-16f);
        float a3 = ex4.w / (dn4.w + 1e-16f);
        if (sub == 0)
            *(float4*)(att_out + (size_t)e * 4) = make_float4(a0, a1, a2, a3);
        const float4* xp = (const float4*)(g_x + (size_t)s * 256) + sub;
        float4 v0 = xp[0], v1 = xp[16], v2 = xp[32], v3 = xp[48];
        float4 m;
        m.x = a0 * v0.x + a1 * v1.x + a2 * v2.x + a3 * v3.x;
        m.y = a0 * v0.y + a1 * v1.y + a2 * v2.y + a3 * v3.y;
        m.z = a0 * v0.z + a1 * v1.z + a2 * v2.z + a3 * v3.z;
        m.w = a0 * v0.w + a1 * v1.w + a2 * v2.w + a3 * v3.w;
        red4(g_out + (size_t)d * 64 + sub * 4, m);
    }
}

// ---------------- group sums of raw out and out^2 (one pass) ---------------
__global__ void k_gsum(const int* __restrict__ bptr) {
    int stride = gridDim.x * blockDim.x;
    for (int idx = blockIdx.x * blockDim.x + threadIdx.x; idx < Nn * 16; idx += stride) {
        int n = idx >> 4, c4 = (idx & 15) << 2;
        int g = bptr[n];
        float4 v = *(const float4*)(g_out + (size_t)n * 64 + c4);
        red4(&g_gsum[g * 64 + c4], v);
        red4(&g_vsum[g * 64 + c4], make_float4(v.x * v.x, v.y * v.y, v.z * v.z, v.w * v.w));
        if ((idx & 15) == 0) atomicAdd(&g_gcnt[g], 1.0f);
    }
}

// ---------------- per (group, channel) mean & rstd -------------------------
// out = raw*0.25 + bias.  o = out - mean*s.
// var = E[out^2] - mean^2 (2s - s^2)  with  E[out^2] = raw2/16 + 0.5*b*raw1 + b^2.
__global__ void k_stats(const float* __restrict__ bias, const float* __restrict__ gns) {
    int idx = blockIdx.x * blockDim.x + threadIdx.x;
    if (idx < Gg * Cc) {
        int c = idx & 63;
        float cnt = fmaxf(g_gcnt[idx >> 6], 1.0f);
        float mr  = g_gsum[idx] / cnt;   // E[raw]
        float m2r = g_vsum[idx] / cnt;   // E[raw^2]
        float b = bias[c], s = gns[c];
        float m = 0.25f * mr + b;        // E[out]
        float Eo2 = 0.0625f * m2r + 0.5f * b * mr + b * b;
        float var = Eo2 - m * m * (2.f * s - s * s);
        g_mean[idx] = m * s;
        g_rstd[idx] = rsqrtf(var + 1e-5f);
    }
}

// ---------------- final normalize + relu -----------------------------------
__global__ void k_final(const int* __restrict__ bptr, const float* __restrict__ bias,
                        const float* __restrict__ gnw, const float* __restrict__ gnb,
                        float* __restrict__ y) {
    int stride = gridDim.x * blockDim.x;
    for (int idx = blockIdx.x * blockDim.x + threadIdx.x; idx < Nn * 16; idx += stride) {
        int n = idx >> 4, c4 = (idx & 15) << 2;
        int g = bptr[n];
        float4 raw = *(const float4*)(g_out + (size_t)n * 64 + c4);
        float4 r;
        float* mm = &g_mean[g * 64 + c4];
        float* rr = &g_rstd[g * 64 + c4];
        {
            float o = raw.x * 0.25f + bias[c4 + 0] - mm[0];
            r.x = fmaxf(gnw[c4 + 0] * (o * rr[0]) + gnb[c4 + 0], 0.f);
        }
        {
            float o = raw.y * 0.25f + bias[c4 + 1] - mm[1];
            r.y = fmaxf(gnw[c4 + 1] * (o * rr[1]) + gnb[c4 + 1], 0.f);
        }
        {
            float o = raw.z * 0.25f + bias[c4 + 2] - mm[2];
            r.z = fmaxf(gnw[c4 + 2] * (o * rr[2]) + gnb[c4 + 2], 0.f);
        }
        {
            float o = raw.w * 0.25f + bias[c4 + 3] - mm[3];
            r.w = fmaxf(gnw[c4 + 3] * (o * rr[3]) + gnb[c4 + 3], 0.f);
        }
        *(float4*)(y + (size_t)n * 64 + c4) = r;
    }
}

// ---------------- launch ----------------
extern "C" void kernel_launch(void* const* d_in, const int* in_sizes, int n_in,
                              void* d_out, int out_size) {
    const float* node = (const float*)d_in[0];
    const int*   ei   = (const int*)  d_in[1];   // [2,E]: src then dst
    const float* ea   = (const float*)d_in[2];
    const int*   bptr = (const int*)  d_in[3];
    const float* W    = (const float*)d_in[4];
    const float* We   = (const float*)d_in[5];
    const float* asv  = (const float*)d_in[6];
    const float* adv  = (const float*)d_in[7];
    const float* aev  = (const float*)d_in[8];
    const float* bias = (const float*)d_in[9];
    const float* gnw  = (const float*)d_in[10];
    const float* gnb  = (const float*)d_in[11];
    const float* gns  = (const float*)d_in[12];

    float* y       = (float*)d_out;           // [N, C] first
    float* att_out = y + (size_t)Nn * Cc;     // [E, H] second

    k_init   <<<2048, 256>>>();
    k_proj   <<<1024, 256>>>(node, W, asv, adv);
    k_medge  <<<1, 64>>>(We, aev);
    k_alpha  <<<2048, 256>>>(ei, ea);
    k_scatter<<<4096, 256>>>(ei, att_out);
    k_gsum   <<<1024, 256>>>(bptr);
    k_stats  <<<16, 256>>>(bias, gns);
    k_final  <<<1024, 256>>>(bptr, bias, gnw, gnb, y);
}

// round 8
// speedup vs baseline: 1.3200x; 1.2522x over previous
#include <cuda_runtime.h>
#include <cstdint>

#define Nn 50000
#define Ee 800000
#define Hh 4
#define Cc 64
#define Gg 64

// ---------------- scratch (device globals: no allocation allowed) ----------
__device__ float g_x[(size_t)Nn * Hh * Cc];   // 51.2 MB projected features
__device__ float g_asrc[Nn * Hh];
__device__ float g_adst[Nn * Hh];
__device__ float g_ex[(size_t)Ee * Hh];       // exp(alpha)
__device__ float g_out[(size_t)Nn * Cc];      // raw aggregated features
__device__ float g_M[16 * 4];                 // edge-attr collapse matrix
__device__ int   g_deg[Nn];                   // in-degree histogram
__device__ int   g_ptr[Nn + 1];               // CSR row pointers (by dst)
__device__ int   g_cursor[Nn];                // fill cursors
__device__ int   g_eidx[Ee];                  // edge ids sorted by dst
__device__ float g_gsum[Gg * Cc];             // sum of raw out per (group, channel)
__device__ float g_vsum[Gg * Cc];             // sum of raw out^2
__device__ float g_mean[Gg * Cc];             // E[out]*gn_scale (pre-multiplied)
__device__ float g_rstd[Gg * Cc];

// ---------------- init ----------------
__global__ void k_init() {
    int stride = gridDim.x * blockDim.x;
    for (int i = blockIdx.x * blockDim.x + threadIdx.x; i < Nn; i += stride) {
        g_deg[i] = 0;
        if (i < Gg * Cc) { g_gsum[i] = 0.f; g_vsum[i] = 0.f; }
    }
}

// ---------------- node projection + attention dot products ----------------
__global__ void k_proj(const float* __restrict__ node, const float* __restrict__ W,
                       const float* __restrict__ att_src, const float* __restrict__ att_dst) {
    const int j = threadIdx.x;
    float w[64];
#pragma unroll
    for (int k = 0; k < 64; k++) w[k] = W[k * 256 + j];
    const float asv = att_src[j];
    const float adv = att_dst[j];

    __shared__ float row[64];
    __shared__ float redS[8], redD[8];
    const int warp = j >> 5, lane = j & 31, h = j >> 6;

    int n = blockIdx.x;
    float4 pre = make_float4(0.f, 0.f, 0.f, 0.f);
    if (n < Nn && j < 16) pre = ((const float4*)(node + (size_t)n * 64))[j];

    while (n < Nn) {
        if (j < 16) ((float4*)row)[j] = pre;
        __syncthreads();
        int nn = n + gridDim.x;
        if (nn < Nn && j < 16) pre = ((const float4*)(node + (size_t)nn * 64))[j];

        float acc = 0.f;
#pragma unroll
        for (int k = 0; k < 64; k++) acc = fmaf(w[k], row[k], acc);
        g_x[(size_t)n * 256 + j] = acc;

        float s = acc * asv, t = acc * adv;
#pragma unroll
        for (int o = 16; o; o >>= 1) {
            s += __shfl_down_sync(0xffffffffu, s, o);
            t += __shfl_down_sync(0xffffffffu, t, o);
        }
        if (lane == 0) { redS[warp] = s; redD[warp] = t; }
        __syncthreads();
        if (lane == 0 && (warp & 1) == 0) {
            g_asrc[n * 4 + h] = redS[warp] + redS[warp + 1];
            g_adst[n * 4 + h] = redD[warp] + redD[warp + 1];
        }
        n = nn;
    }
}

// ---------------- edge-attr collapse matrix M[16,4] ----------------
__global__ void k_medge(const float* __restrict__ We, const float* __restrict__ ae) {
    int t = threadIdx.x;            // 0..63
    int d = t >> 2, h = t & 3;
    float s = 0.f;
    for (int c = 0; c < 64; c++) s += We[d * 256 + h * 64 + c] * ae[h * 64 + c];
    g_M[d * 4 + h] = s;
}

// ---- ex = exp(leaky(a_src[s]+a_dst[d]+ea@M)); in-degree histogram ---------
// No max subtraction: exp(a-m)/sum == exp(a)/sum; |alpha| small so fp32 safe.
__global__ void k_alpha(const int* __restrict__ ei, const float* __restrict__ ea) {
    __shared__ float Ms[64];
    if (threadIdx.x < 64) Ms[threadIdx.x] = g_M[threadIdx.x];
    __syncthreads();
    int stride = gridDim.x * blockDim.x;
    for (int e = blockIdx.x * blockDim.x + threadIdx.x; e < Ee; e += stride) {
        int s = ei[e], d = ei[Ee + e];
        float aeh[4] = {0.f, 0.f, 0.f, 0.f};
        const float4* ep = (const float4*)(ea + (size_t)e * 16);
#pragma unroll
        for (int q = 0; q < 4; q++) {
            float4 v = ep[q];
#pragma unroll
            for (int h = 0; h < 4; h++) {
                aeh[h] += v.x * Ms[(q * 4 + 0) * 4 + h]
                        + v.y * Ms[(q * 4 + 1) * 4 + h]
                        + v.z * Ms[(q * 4 + 2) * 4 + h]
                        + v.w * Ms[(q * 4 + 3) * 4 + h];
            }
        }
        float4 as4 = *(const float4*)(g_asrc + s * 4);
        float4 ad4 = *(const float4*)(g_adst + d * 4);
        float al0 = as4.x + ad4.x + aeh[0];
        float al1 = as4.y + ad4.y + aeh[1];
        float al2 = as4.z + ad4.z + aeh[2];
        float al3 = as4.w + ad4.w + aeh[3];
        al0 = (al0 > 0.f) ? al0 : 0.2f * al0;
        al1 = (al1 > 0.f) ? al1 : 0.2f * al1;
        al2 = (al2 > 0.f) ? al2 : 0.2f * al2;
        al3 = (al3 > 0.f) ? al3 : 0.2f * al3;
        *(float4*)(g_ex + (size_t)e * 4) =
            make_float4(__expf(al0), __expf(al1), __expf(al2), __expf(al3));
        atomicAdd(&g_deg[d], 1);
    }
}

// ---------------- exclusive scan of degrees (single block, 1024 thr) -------
__global__ void k_scan() {
    __shared__ int wsum[32];
    __shared__ int s_carry;
    const int t = threadIdx.x, lane = t & 31, w = t >> 5;
    if (t == 0) s_carry = 0;
    __syncthreads();
    for (int base = 0; base < Nn; base += 1024) {
        int i = base + t;
        int v = (i < Nn) ? g_deg[i] : 0;
        int x = v;
#pragma unroll
        for (int o = 1; o < 32; o <<= 1) {
            int y = __shfl_up_sync(0xffffffffu, x, o);
            if (lane >= o) x += y;
        }
        if (lane == 31) wsum[w] = x;
        __syncthreads();
        if (w == 0) {
            int y = wsum[lane];
#pragma unroll
            for (int o = 1; o < 32; o <<= 1) {
                int z = __shfl_up_sync(0xffffffffu, y, o);
                if (lane >= o) y += z;
            }
            wsum[lane] = y;
        }
        __syncthreads();
        int incl = x + (w ? wsum[w - 1] : 0) + s_carry;
        if (i < Nn) { int ex = incl - v; g_ptr[i] = ex; g_cursor[i] = ex; }
        __syncthreads();
        if (t == 1023) s_carry = incl;
        __syncthreads();
    }
    if (t == 0) g_ptr[Nn] = s_carry;
}

// ---------------- CSR fill: bucket edge ids by dst -------------------------
__global__ void k_fill(const int* __restrict__ ei) {
    int stride = gridDim.x * blockDim.x;
    for (int e = blockIdx.x * blockDim.x + threadIdx.x; e < Ee; e += stride) {
        int d = ei[Ee + e];
        int pos = atomicAdd(&g_cursor[d], 1);
        g_eidx[pos] = e;
    }
}

// ---------------- gather: one warp per dst node, NO float atomics ----------
// Two edges processed per step (half-warp each); per-head accumulators so
// the softmax division happens once at the end.
__global__ void k_gather(const int* __restrict__ ei, float* __restrict__ att_out) {
    int gw = (blockIdx.x * blockDim.x + threadIdx.x) >> 5;
    if (gw >= Nn) return;
    const int lane = threadIdx.x & 31;
    const int half = lane >> 4, sub = lane & 15;
    const int n = gw;
    const int beg = g_ptr[n], end = g_ptr[n + 1];

    float4 acc0 = make_float4(0,0,0,0), acc1 = acc0, acc2 = acc0, acc3 = acc0;
    float d0 = 0.f, d1 = 0.f, d2 = 0.f, d3 = 0.f;

    for (int base = beg; base < end; base += 32) {
        int m = min(32, end - base);
        int s = 0; float4 ex4 = make_float4(0,0,0,0);
        if (lane < m) {
            int e = g_eidx[base + lane];
            s = ei[e];
            ex4 = *(const float4*)(g_ex + (size_t)e * 4);
        }
        int steps = (m + 1) >> 1;
        for (int k = 0; k < steps; k++) {
            int idx = 2 * k + half;
            int ss  = __shfl_sync(0xffffffffu, s, idx);
            float ex0 = __shfl_sync(0xffffffffu, ex4.x, idx);
            float ex1 = __shfl_sync(0xffffffffu, ex4.y, idx);
            float ex2 = __shfl_sync(0xffffffffu, ex4.z, idx);
            float ex3 = __shfl_sync(0xffffffffu, ex4.w, idx);
            if (idx < m) {
                const float4* xp = (const float4*)(g_x + (size_t)ss * 256) + sub;
                float4 v0 = xp[0], v1 = xp[16], v2 = xp[32], v3 = xp[48];
                acc0.x = fmaf(ex0, v0.x, acc0.x); acc0.y = fmaf(ex0, v0.y, acc0.y);
                acc0.z = fmaf(ex0, v0.z, acc0.z); acc0.w = fmaf(ex0, v0.w, acc0.w);
                acc1.x = fmaf(ex1, v1.x, acc1.x); acc1.y = fmaf(ex1, v1.y, acc1.y);
                acc1.z = fmaf(ex1, v1.z, acc1.z); acc1.w = fmaf(ex1, v1.w, acc1.w);
                acc2.x = fmaf(ex2, v2.x, acc2.x); acc2.y = fmaf(ex2, v2.y, acc2.y);
                acc2.z = fmaf(ex2, v2.z, acc2.z); acc2.w = fmaf(ex2, v2.w, acc2.w);
                acc3.x = fmaf(ex3, v3.x, acc3.x); acc3.y = fmaf(ex3, v3.y, acc3.y);
                acc3.z = fmaf(ex3, v3.z, acc3.z); acc3.w = fmaf(ex3, v3.w, acc3.w);
                d0 += ex0; d1 += ex1; d2 += ex2; d3 += ex3;
            }
        }
    }
    // combine the two half-warp accumulators
    acc0.x += __shfl_xor_sync(0xffffffffu, acc0.x, 16);
    acc0.y += __shfl_xor_sync(0xffffffffu, acc0.y, 16);
    acc0.z += __shfl_xor_sync(0xffffffffu, acc0.z, 16);
    acc0.w += __shfl_xor_sync(0xffffffffu, acc0.w, 16);
    acc1.x += __shfl_xor_sync(0xffffffffu, acc1.x, 16);
    acc1.y += __shfl_xor_sync(0xffffffffu, acc1.y, 16);
    acc1.z += __shfl_xor_sync(0xffffffffu, acc1.z, 16);
    acc1.w += __shfl_xor_sync(0xffffffffu, acc1.w, 16);
    acc2.x += __shfl_xor_sync(0xffffffffu, acc2.x, 16);
    acc2.y += __shfl_xor_sync(0xffffffffu, acc2.y, 16);
    acc2.z += __shfl_xor_sync(0xffffffffu, acc2.z, 16);
    acc2.w += __shfl_xor_sync(0xffffffffu, acc2.w, 16);
    acc3.x += __shfl_xor_sync(0xffffffffu, acc3.x, 16);
    acc3.y += __shfl_xor_sync(0xffffffffu, acc3.y, 16);
    acc3.z += __shfl_xor_sync(0xffffffffu, acc3.z, 16);
    acc3.w += __shfl_xor_sync(0xffffffffu, acc3.w, 16);
    d0 += __shfl_xor_sync(0xffffffffu, d0, 16);
    d1 += __shfl_xor_sync(0xffffffffu, d1, 16);
    d2 += __shfl_xor_sync(0xffffffffu, d2, 16);
    d3 += __shfl_xor_sync(0xffffffffu, d3, 16);

    float i0 = 1.f / (d0 + 1e-16f);
    float i1 = 1.f / (d1 + 1e-16f);
    float i2 = 1.f / (d2 + 1e-16f);
    float i3 = 1.f / (d3 + 1e-16f);

    if (half == 0) {
        float4 o;
        o.x = acc0.x * i0 + acc1.x * i1 + acc2.x * i2 + acc3.x * i3;
        o.y = acc0.y * i0 + acc1.y * i1 + acc2.y * i2 + acc3.y * i3;
        o.z = acc0.z * i0 + acc1.z * i1 + acc2.z * i2 + acc3.z * i3;
        o.w = acc0.w * i0 + acc1.w * i1 + acc2.w * i2 + acc3.w * i3;
        *(float4*)(g_out + (size_t)n * 64 + sub * 4) = o;
    }
    // normalized attention output per edge
    for (int j = beg + lane; j < end; j += 32) {
        int e = g_eidx[j];
        float4 ex4 = *(const float4*)(g_ex + (size_t)e * 4);
        *(float4*)(att_out + (size_t)e * 4) =
            make_float4(ex4.x * i0, ex4.y * i1, ex4.z * i2, ex4.w * i3);
    }
}

// ------- group sums of raw out / out^2: sorted-bptr run accumulation -------
// 500 blocks x 100 nodes; thread = (channel, node-slot). Flush on group change.
#define GS_CH 100
__global__ void k_gsum(const int* __restrict__ bptr) {
    const int t = threadIdx.x;
    const int c = t & 63, slot = t >> 6;          // 4 node lanes
    int n = blockIdx.x * GS_CH + slot;
    int nend = min(blockIdx.x * GS_CH + GS_CH, Nn);
    if (n >= nend) return;
    int gcur = bptr[n];
    float sum = 0.f, sq = 0.f;
    for (; n < nend; n += 4) {
        int g = bptr[n];
        if (g != gcur) {
            atomicAdd(&g_gsum[gcur * 64 + c], sum);
            atomicAdd(&g_vsum[gcur * 64 + c], sq);
            gcur = g; sum = 0.f; sq = 0.f;
        }
        float v = g_out[(size_t)n * 64 + c];
        sum += v; sq = fmaf(v, v, sq);
    }
    atomicAdd(&g_gsum[gcur * 64 + c], sum);
    atomicAdd(&g_vsum[gcur * 64 + c], sq);
}

// ---------------- per (group, channel) mean & rstd -------------------------
// cnt via binary search on sorted bptr (no atomics).
__global__ void k_stats(const int* __restrict__ bptr, const float* __restrict__ bias,
                        const float* __restrict__ gns) {
    int idx = blockIdx.x * blockDim.x + threadIdx.x;
    if (idx >= Gg * Cc) return;
    int g = idx >> 6, c = idx & 63;
    // lower bound of g
    int lo = 0, hi = Nn;
    while (lo < hi) { int mid = (lo + hi) >> 1; if (bptr[mid] < g) lo = mid + 1; else hi = mid; }
    int first = lo;
    lo = first; hi = Nn;
    while (lo < hi) { int mid = (lo + hi) >> 1; if (bptr[mid] <= g) lo = mid + 1; else hi = mid; }
    float cnt = fmaxf((float)(lo - first), 1.0f);

    float mr  = g_gsum[idx] / cnt;   // E[raw]
    float m2r = g_vsum[idx] / cnt;   // E[raw^2]
    float b = bias[c], s = gns[c];
    float m = 0.25f * mr + b;        // E[out]
    float Eo2 = 0.0625f * m2r + 0.5f * b * mr + b * b;
    float var = Eo2 - m * m * (2.f * s - s * s);
    g_mean[idx] = m * s;
    g_rstd[idx] = rsqrtf(var + 1e-5f);
}

// ---------------- final normalize + relu -----------------------------------
__global__ void k_final(const int* __restrict__ bptr, const float* __restrict__ bias,
                        const float* __restrict__ gnw, const float* __restrict__ gnb,
                        float* __restrict__ y) {
    int stride = gridDim.x * blockDim.x;
    for (int idx = blockIdx.x * blockDim.x + threadIdx.x; idx < Nn * 16; idx += stride) {
        int n = idx >> 4, c4 = (idx & 15) << 2;
        int g = bptr[n];
        float4 raw = *(const float4*)(g_out + (size_t)n * 64 + c4);
        float* mm = &g_mean[g * 64 + c4];
        float* rr = &g_rstd[g * 64 + c4];
        float4 r;
        { float o = raw.x * 0.25f + bias[c4 + 0] - mm[0];
          r.x = fmaxf(gnw[c4 + 0] * (o * rr[0]) + gnb[c4 + 0], 0.f); }
        { float o = raw.y * 0.25f + bias[c4 + 1] - mm[1];
          r.y = fmaxf(gnw[c4 + 1] * (o * rr[1]) + gnb[c4 + 1], 0.f); }
        { float o = raw.z * 0.25f + bias[c4 + 2] - mm[2];
          r.z = fmaxf(gnw[c4 + 2] * (o * rr[2]) + gnb[c4 + 2], 0.f); }
        { float o = raw.w * 0.25f + bias[c4 + 3] - mm[3];
          r.w = fmaxf(gnw[c4 + 3] * (o * rr[3]) + gnb[c4 + 3], 0.f); }
        *(float4*)(y + (size_t)n * 64 + c4) = r;
    }
}

// ---------------- launch ----------------
extern "C" void kernel_launch(void* const* d_in, const int* in_sizes, int n_in,
                              void* d_out, int out_size) {
    const float* node = (const float*)d_in[0];
    const int*   ei   = (const int*)  d_in[1];   // [2,E]: src then dst
    const float* ea   = (const float*)d_in[2];
    const int*   bptr = (const int*)  d_in[3];
    const float* W    = (const float*)d_in[4];
    const float* We   = (const float*)d_in[5];
    const float* asv  = (const float*)d_in[6];
    const float* adv  = (const float*)d_in[7];
    const float* aev  = (const float*)d_in[8];
    const float* bias = (const float*)d_in[9];
    const float* gnw  = (const float*)d_in[10];
    const float* gnb  = (const float*)d_in[11];
    const float* gns  = (const float*)d_in[12];

    float* y       = (float*)d_out;           // [N, C] first
    float* att_out = y + (size_t)Nn * Cc;     // [E, H] second

    k_init  <<<256, 256>>>();
    k_proj  <<<1024, 256>>>(node, W, asv, adv);
    k_medge <<<1, 64>>>(We, aev);
    k_alpha <<<2048, 256>>>(ei, ea);
    k_scan  <<<1, 1024>>>();
    k_fill  <<<2048, 256>>>(ei);
    k_gather<<<(Nn * 32 + 255) / 256, 256>>>(ei, att_out);
    k_gsum  <<<(Nn + GS_CH - 1) / GS_CH, 256>>>(bptr);
    k_stats <<<16, 256>>>(bptr, bias, gns);
    k_final <<<1024, 256>>>(bptr, bias, gnw, gnb, y);
}

// round 13
// speedup vs baseline: 1.4930x; 1.1311x over previous
#include <cuda_runtime.h>
#include <cstdint>

#define Nn 50000
#define Ee 800000
#define Hh 4
#define Cc 64
#define Gg 64
#define SCAN_NB 196   // ceil(50000/256)

// ---------------- scratch (device globals: no allocation allowed) ----------
__device__ float  g_x[(size_t)Nn * Hh * Cc];  // 51.2 MB projected features
__device__ float  g_asrc[Nn * Hh];
__device__ float  g_adst[Nn * Hh];
__device__ float  g_out[(size_t)Nn * Cc];     // raw aggregated features
__device__ float  g_M[16 * 4];                // edge-attr collapse matrix
__device__ int    g_deg[Nn];                  // in-degree histogram
__device__ int    g_ptr[Nn + 1];              // CSR row pointers (by dst)
__device__ int    g_cursor[Nn];               // fill cursors
__device__ int    g_bsum[SCAN_NB];            // scan block sums
__device__ int    g_boff[SCAN_NB];            // scan block offsets
__device__ int    g_ssrc[Ee];                 // src node, sorted by dst
__device__ int    g_seid[Ee];                 // original edge id, sorted by dst
__device__ float4 g_sex[Ee];                  // exp(alpha) 4 heads, sorted by dst
__device__ float  g_gsum[Gg * Cc];            // sum of raw out per (group, channel)
__device__ float  g_vsum[Gg * Cc];            // sum of raw out^2
__device__ float  g_mean[Gg * Cc];            // E[out]*gn_scale (pre-multiplied)
__device__ float  g_rstd[Gg * Cc];

// ---------------- init ----------------
__global__ void k_init() {
    int stride = gridDim.x * blockDim.x;
    for (int i = blockIdx.x * blockDim.x + threadIdx.x; i < Nn; i += stride) {
        g_deg[i] = 0;
        if (i < Gg * Cc) { g_gsum[i] = 0.f; g_vsum[i] = 0.f; }
    }
}

// ---------------- in-degree histogram (vectorized) -------------------------
__global__ void k_deg(const int* __restrict__ ei) {
    int i = blockIdx.x * blockDim.x + threadIdx.x;
    if (i < Ee / 4) {
        int4 d = ((const int4*)(ei + Ee))[i];
        atomicAdd(&g_deg[d.x], 1);
        atomicAdd(&g_deg[d.y], 1);
        atomicAdd(&g_deg[d.z], 1);
        atomicAdd(&g_deg[d.w], 1);
    }
}

// ---------------- scan phase 1: per-block exclusive scan + block sums ------
__global__ void k_scan1() {
    __shared__ int wsum[8];
    const int t = threadIdx.x, lane = t & 31, w = t >> 5;
    int idx = blockIdx.x * 256 + t;
    int v = (idx < Nn) ? g_deg[idx] : 0;
    int x = v;
#pragma unroll
    for (int o = 1; o < 32; o <<= 1) {
        int y = __shfl_up_sync(0xffffffffu, x, o);
        if (lane >= o) x += y;
    }
    if (lane == 31) wsum[w] = x;
    __syncthreads();
    if (w == 0 && lane < 8) {
        int y = wsum[lane];
#pragma unroll
        for (int o = 1; o < 8; o <<= 1) {
            int z = __shfl_up_sync(0xffu, y, o);
            if (lane >= o) y += z;
        }
        wsum[lane] = y;
    }
    __syncthreads();
    int incl = x + (w ? wsum[w - 1] : 0);
    if (idx < Nn) g_ptr[idx] = incl - v;      // local exclusive
    if (t == 255) g_bsum[blockIdx.x] = incl;  // block total
}

// ---------------- scan phase 2: scan the block sums (1 block) --------------
__global__ void k_scan2() {
    __shared__ int wsum[8];
    const int t = threadIdx.x, lane = t & 31, w = t >> 5;
    int v = (t < SCAN_NB) ? g_bsum[t] : 0;
    int x = v;
#pragma unroll
    for (int o = 1; o < 32; o <<= 1) {
        int y = __shfl_up_sync(0xffffffffu, x, o);
        if (lane >= o) x += y;
    }
    if (lane == 31) wsum[w] = x;
    __syncthreads();
    if (w == 0 && lane < 8) {
        int y = wsum[lane];
#pragma unroll
        for (int o = 1; o < 8; o <<= 1) {
            int z = __shfl_up_sync(0xffu, y, o);
            if (lane >= o) y += z;
        }
        wsum[lane] = y;
    }
    __syncthreads();
    int incl = x + (w ? wsum[w - 1] : 0);
    if (t < SCAN_NB) g_boff[t] = incl - v;
    if (t == 255) g_ptr[Nn] = incl;           // grand total (= Ee)
}

// ---------------- scan phase 3: add offsets, init cursors ------------------
__global__ void k_scan3() {
    int idx = blockIdx.x * 256 + threadIdx.x;
    if (idx < Nn) {
        int p = g_ptr[idx] + g_boff[blockIdx.x];
        g_ptr[idx] = p;
        g_cursor[idx] = p;
    }
}

// ---------------- node projection + attention dot products ----------------
__global__ void k_proj(const float* __restrict__ node, const float* __restrict__ W,
                       const float* __restrict__ att_src, const float* __restrict__ att_dst) {
    const int j = threadIdx.x;
    float w[64];
#pragma unroll
    for (int k = 0; k < 64; k++) w[k] = W[k * 256 + j];
    const float asv = att_src[j];
    const float adv = att_dst[j];

    __shared__ float row[64];
    __shared__ float redS[8], redD[8];
    const int warp = j >> 5, lane = j & 31, h = j >> 6;

    int n = blockIdx.x;
    float4 pre = make_float4(0.f, 0.f, 0.f, 0.f);
    if (n < Nn && j < 16) pre = ((const float4*)(node + (size_t)n * 64))[j];

    while (n < Nn) {
        if (j < 16) ((float4*)row)[j] = pre;
        __syncthreads();
        int nn = n + gridDim.x;
        if (nn < Nn && j < 16) pre = ((const float4*)(node + (size_t)nn * 64))[j];

        float acc = 0.f;
#pragma unroll
        for (int k = 0; k < 64; k++) acc = fmaf(w[k], row[k], acc);
        g_x[(size_t)n * 256 + j] = acc;

        float s = acc * asv, t = acc * adv;
#pragma unroll
        for (int o = 16; o; o >>= 1) {
            s += __shfl_down_sync(0xffffffffu, s, o);
            t += __shfl_down_sync(0xffffffffu, t, o);
        }
        if (lane == 0) { redS[warp] = s; redD[warp] = t; }
        __syncthreads();
        if (lane == 0 && (warp & 1) == 0) {
            g_asrc[n * 4 + h] = redS[warp] + redS[warp + 1];
            g_adst[n * 4 + h] = redD[warp] + redD[warp + 1];
        }
        n = nn;
    }
}

// ---------------- edge-attr collapse matrix M[16,4] ----------------
__global__ void k_medge(const float* __restrict__ We, const float* __restrict__ ae) {
    int t = threadIdx.x;            // 0..63
    int d = t >> 2, h = t & 3;
    float s = 0.f;
    for (int c = 0; c < 64; c++) s += We[d * 256 + h * 64 + c] * ae[h * 64 + c];
    g_M[d * 4 + h] = s;
}

// ---- ex = exp(leaky(a_src[s]+a_dst[d]+ea@M)); write payload CSR-sorted ----
// No max subtraction: exp(a-m)/sum == exp(a)/sum; |alpha| small so fp32 safe.
__global__ void __launch_bounds__(256, 4)
k_alpha(const int* __restrict__ ei, const float* __restrict__ ea) {
    __shared__ float Ms[64];
    if (threadIdx.x < 64) Ms[threadIdx.x] = g_M[threadIdx.x];
    __syncthreads();
    int stride = gridDim.x * blockDim.x;
    for (int e = blockIdx.x * blockDim.x + threadIdx.x; e < Ee; e += stride) {
        int s = ei[e], d = ei[Ee + e];
        float aeh[4] = {0.f, 0.f, 0.f, 0.f};
        const float4* ep = (const float4*)(ea + (size_t)e * 16);
#pragma unroll
        for (int q = 0; q < 4; q++) {
            float4 v = ep[q];
#pragma unroll
            for (int h = 0; h < 4; h++) {
                aeh[h] += v.x * Ms[(q * 4 + 0) * 4 + h]
                        + v.y * Ms[(q * 4 + 1) * 4 + h]
                        + v.z * Ms[(q * 4 + 2) * 4 + h]
                        + v.w * Ms[(q * 4 + 3) * 4 + h];
            }
        }
        float4 as4 = *(const float4*)(g_asrc + s * 4);
        float4 ad4 = *(const float4*)(g_adst + d * 4);
        float al0 = as4.x + ad4.x + aeh[0];
        float al1 = as4.y + ad4.y + aeh[1];
        float al2 = as4.z + ad4.z + aeh[2];
        float al3 = as4.w + ad4.w + aeh[3];
        al0 = (al0 > 0.f) ? al0 : 0.2f * al0;
        al1 = (al1 > 0.f) ? al1 : 0.2f * al1;
        al2 = (al2 > 0.f) ? al2 : 0.2f * al2;
        al3 = (al3 > 0.f) ? al3 : 0.2f * al3;
        int pos = atomicAdd(&g_cursor[d], 1);
        g_ssrc[pos] = s;
        g_seid[pos] = e;
        g_sex[pos] = make_float4(__expf(al0), __expf(al1), __expf(al2), __expf(al3));
    }
}

// ---------------- gather: one warp per dst node, NO float atomics ----------
// Half-warp per edge; payload reads are broadcast/coalesced (sorted arrays).
__global__ void k_gather(float* __restrict__ att_out) {
    int gw = (blockIdx.x * blockDim.x + threadIdx.x) >> 5;
    if (gw >= Nn) return;
    const int lane = threadIdx.x & 31;
    const int half = lane >> 4, sub = lane & 15;
    const int beg = g_ptr[gw], end = g_ptr[gw + 1];

    float4 acc0 = make_float4(0,0,0,0), acc1 = acc0, acc2 = acc0, acc3 = acc0;
    float d0 = 0.f, d1 = 0.f, d2 = 0.f, d3 = 0.f;

    for (int j = beg + half; j < end; j += 2) {
        int s = g_ssrc[j];            // broadcast within half-warp
        float4 ex = g_sex[j];
        const float4* xp = (const float4*)(g_x + (size_t)s * 256) + sub;
        float4 v0 = xp[0], v1 = xp[16], v2 = xp[32], v3 = xp[48];
        acc0.x = fmaf(ex.x, v0.x, acc0.x); acc0.y = fmaf(ex.x, v0.y, acc0.y);
        acc0.z = fmaf(ex.x, v0.z, acc0.z); acc0.w = fmaf(ex.x, v0.w, acc0.w);
        acc1.x = fmaf(ex.y, v1.x, acc1.x); acc1.y = fmaf(ex.y, v1.y, acc1.y);
        acc1.z = fmaf(ex.y, v1.z, acc1.z); acc1.w = fmaf(ex.y, v1.w, acc1.w);
        acc2.x = fmaf(ex.z, v2.x, acc2.x); acc2.y = fmaf(ex.z, v2.y, acc2.y);
        acc2.z = fmaf(ex.z, v2.z, acc2.z); acc2.w = fmaf(ex.z, v2.w, acc2.w);
        acc3.x = fmaf(ex.w, v3.x, acc3.x); acc3.y = fmaf(ex.w, v3.y, acc3.y);
        acc3.z = fmaf(ex.w, v3.z, acc3.z); acc3.w = fmaf(ex.w, v3.w, acc3.w);
        d0 += ex.x; d1 += ex.y; d2 += ex.z; d3 += ex.w;
    }
    // combine the two half-warp accumulators
    acc0.x += __shfl_xor_sync(0xffffffffu, acc0.x, 16);
    acc0.y += __shfl_xor_sync(0xffffffffu, acc0.y, 16);
    acc0.z += __shfl_xor_sync(0xffffffffu, acc0.z, 16);
    acc0.w += __shfl_xor_sync(0xffffffffu, acc0.w, 16);
    acc1.x += __shfl_xor_sync(0xffffffffu, acc1.x, 16);
    acc1.y += __shfl_xor_sync(0xffffffffu, acc1.y, 16);
    acc1.z += __shfl_xor_sync(0xffffffffu, acc1.z, 16);
    acc1.w += __shfl_xor_sync(0xffffffffu, acc1.w, 16);
    acc2.x += __shfl_xor_sync(0xffffffffu, acc2.x, 16);
    acc2.y += __shfl_xor_sync(0xffffffffu, acc2.y, 16);
    acc2.z += __shfl_xor_sync(0xffffffffu, acc2.z, 16);
    acc2.w += __shfl_xor_sync(0xffffffffu, acc2.w, 16);
    acc3.x += __shfl_xor_sync(0xffffffffu, acc3.x, 16);
    acc3.y += __shfl_xor_sync(0xffffffffu, acc3.y, 16);
    acc3.z += __shfl_xor_sync(0xffffffffu, acc3.z, 16);
    acc3.w += __shfl_xor_sync(0xffffffffu, acc3.w, 16);
    d0 += __shfl_xor_sync(0xffffffffu, d0, 16);
    d1 += __shfl_xor_sync(0xffffffffu, d1, 16);
    d2 += __shfl_xor_sync(0xffffffffu, d2, 16);
    d3 += __shfl_xor_sync(0xffffffffu, d3, 16);

    float i0 = 1.f / (d0 + 1e-16f);
    float i1 = 1.f / (d1 + 1e-16f);
    float i2 = 1.f / (d2 + 1e-16f);
    float i3 = 1.f / (d3 + 1e-16f);

    if (half == 0) {
        float4 o;
        o.x = acc0.x * i0 + acc1.x * i1 + acc2.x * i2 + acc3.x * i3;
        o.y = acc0.y * i0 + acc1.y * i1 + acc2.y * i2 + acc3.y * i3;
        o.z = acc0.z * i0 + acc1.z * i1 + acc2.z * i2 + acc3.z * i3;
        o.w = acc0.w * i0 + acc1.w * i1 + acc2.w * i2 + acc3.w * i3;
        *(float4*)(g_out + (size_t)gw * 64 + sub * 4) = o;
    }
    // normalized attention, scattered back to original edge order
    for (int j = beg + lane; j < end; j += 32) {
        int e = g_seid[j];
        float4 ex = g_sex[j];
        *(float4*)(att_out + (size_t)e * 4) =
            make_float4(ex.x * i0, ex.y * i1, ex.z * i2, ex.w * i3);
    }
}

// ------- group sums of raw out / out^2: sorted-bptr run accumulation -------
#define GS_CH 100
__global__ void k_gsum(const int* __restrict__ bptr) {
    const int t = threadIdx.x;
    const int c = t & 63, slot = t >> 6;          // 4 node lanes
    int n = blockIdx.x * GS_CH + slot;
    int nend = min(blockIdx.x * GS_CH + GS_CH, Nn);
    if (n >= nend) return;
    int gcur = bptr[n];
    float sum = 0.f, sq = 0.f;
    for (; n < nend; n += 4) {
        int g = bptr[n];
        if (g != gcur) {
            atomicAdd(&g_gsum[gcur * 64 + c], sum);
            atomicAdd(&g_vsum[gcur * 64 + c], sq);
            gcur = g; sum = 0.f; sq = 0.f;
        }
        float v = g_out[(size_t)n * 64 + c];
        sum += v; sq = fmaf(v, v, sq);
    }
    atomicAdd(&g_gsum[gcur * 64 + c], sum);
    atomicAdd(&g_vsum[gcur * 64 + c], sq);
}

// ---------------- per (group, channel) mean & rstd -------------------------
__global__ void k_stats(const int* __restrict__ bptr, const float* __restrict__ bias,
                        const float* __restrict__ gns) {
    int idx = blockIdx.x * blockDim.x + threadIdx.x;
    if (idx >= Gg * Cc) return;
    int g = idx >> 6, c = idx & 63;
    int lo = 0, hi = Nn;
    while (lo < hi) { int mid = (lo + hi) >> 1; if (bptr[mid] < g) lo = mid + 1; else hi = mid; }
    int first = lo;
    lo = first; hi = Nn;
    while (lo < hi) { int mid = (lo + hi) >> 1; if (bptr[mid] <= g) lo = mid + 1; else hi = mid; }
    float cnt = fmaxf((float)(lo - first), 1.0f);

    float mr  = g_gsum[idx] / cnt;   // E[raw]
    float m2r = g_vsum[idx] / cnt;   // E[raw^2]
    float b = bias[c], s = gns[c];
    float m = 0.25f * mr + b;        // E[out]
    float Eo2 = 0.0625f * m2r + 0.5f * b * mr + b * b;
    float var = Eo2 - m * m * (2.f * s - s * s);
    g_mean[idx] = m * s;
    g_rstd[idx] = rsqrtf(var + 1e-5f);
}

// ---------------- final normalize + relu -----------------------------------
__global__ void k_final(const int* __restrict__ bptr, const float* __restrict__ bias,
                        const float* __restrict__ gnw, const float* __restrict__ gnb,
                        float* __restrict__ y) {
    int stride = gridDim.x * blockDim.x;
    for (int idx = blockIdx.x * blockDim.x + threadIdx.x; idx < Nn * 16; idx += stride) {
        int n = idx >> 4, c4 = (idx & 15) << 2;
        int g = bptr[n];
        float4 raw = *(const float4*)(g_out + (size_t)n * 64 + c4);
        float* mm = &g_mean[g * 64 + c4];
        float* rr = &g_rstd[g * 64 + c4];
        float4 r;
        { float o = raw.x * 0.25f + bias[c4 + 0] - mm[0];
          r.x = fmaxf(gnw[c4 + 0] * (o * rr[0]) + gnb[c4 + 0], 0.f); }
        { float o = raw.y * 0.25f + bias[c4 + 1] - mm[1];
          r.y = fmaxf(gnw[c4 + 1] * (o * rr[1]) + gnb[c4 + 1], 0.f); }
        { float o = raw.z * 0.25f + bias[c4 + 2] - mm[2];
          r.z = fmaxf(gnw[c4 + 2] * (o * rr[2]) + gnb[c4 + 2], 0.f); }
        { float o = raw.w * 0.25f + bias[c4 + 3] - mm[3];
          r.w = fmaxf(gnw[c4 + 3] * (o * rr[3]) + gnb[c4 + 3], 0.f); }
        *(float4*)(y + (size_t)n * 64 + c4) = r;
    }
}

// ---------------- launch ----------------
extern "C" void kernel_launch(void* const* d_in, const int* in_sizes, int n_in,
                              void* d_out, int out_size) {
    const float* node = (const float*)d_in[0];
    const int*   ei   = (const int*)  d_in[1];   // [2,E]: src then dst
    const float* ea   = (const float*)d_in[2];
    const int*   bptr = (const int*)  d_in[3];
    const float* W    = (const float*)d_in[4];
    const float* We   = (const float*)d_in[5];
    const float* asv  = (const float*)d_in[6];
    const float* adv  = (const float*)d_in[7];
    const float* aev  = (const float*)d_in[8];
    const float* bias = (const float*)d_in[9];
    const float* gnw  = (const float*)d_in[10];
    const float* gnb  = (const float*)d_in[11];
    const float* gns  = (const float*)d_in[12];

    float* y       = (float*)d_out;           // [N, C] first
    float* att_out = y + (size_t)Nn * Cc;     // [E, H] second

    k_init  <<<256, 256>>>();
    k_deg   <<<(Ee / 4 + 255) / 256, 256>>>(ei);
    k_scan1 <<<SCAN_NB, 256>>>();
    k_scan2 <<<1, 256>>>();
    k_scan3 <<<SCAN_NB, 256>>>();
    k_proj  <<<1024, 256>>>(node, W, asv, adv);
    k_medge <<<1, 64>>>(We, aev);
    k_alpha <<<2048, 256>>>(ei, ea);
    k_gather<<<(Nn * 32 + 255) / 256, 256>>>(att_out);
    k_gsum  <<<(Nn + GS_CH - 1) / GS_CH, 256>>>(bptr);
    k_stats <<<16, 256>>>(bptr, bias, gns);
    k_final <<<1024, 256>>>(bptr, bias, gnw, gnb, y);
}